// round 15
// baseline (speedup 1.0000x reference)
#include <cuda_runtime.h>
#include <cuda_bf16.h>
#include <cstdint>

#define DFEAT 128
#define MAX_NODES 100000
#define MAX_EDGES 650000
#define BLD_BLK 512
#define BLD_NB  444          // 3 blocks/SM on 148 SMs; all co-resident
#define MAX_BLD 512

// scratch (static __device__ arrays — no allocations allowed)
__device__ int          g_deg[MAX_NODES];
__device__ int          g_off[MAX_NODES];
__device__ float        g_dinv[MAX_NODES];
__device__ int          g_adj[2 * MAX_EDGES];
// persistent-kernel sync state; statically zero, re-zeroed by k_gg each launch
__device__ volatile int g_sctr[4];
__device__ volatile int g_flag[MAX_BLD];
__device__ volatile int g_aggr[MAX_BLD];
__device__ int          g_is64;

// ---------------------------------------------------------------------------
// Grid sync via atomic counter + spin. SAFE only because all BLD_NB blocks
// are co-resident (444 = 3/SM, 512 thr).
// ---------------------------------------------------------------------------
__device__ __forceinline__ void grid_sync(int k, int nb) {
    __syncthreads();
    if (threadIdx.x == 0) {
        __threadfence();
        atomicAdd((int*)&g_sctr[k], 1);
        while (g_sctr[k] < nb) { }
        __threadfence();
    }
    __syncthreads();
}

// ---------------------------------------------------------------------------
// Kernel 1 (fused persistent): zero+detect -> histogram -> scan(+dinv) -> scatter
// ---------------------------------------------------------------------------
__global__ __launch_bounds__(BLD_BLK)
void k_build(const int* __restrict__ ei_w, int n, int E, int nb) {
    __shared__ int ws[16];
    __shared__ int sbase;
    int tid  = threadIdx.x;
    int bid  = blockIdx.x;
    int lane = tid & 31, wid = tid >> 5;
    int gtid = bid * BLD_BLK + tid;
    int nthr = nb * BLD_BLK;

    // phase 0: zero degree counters; block 0 detects edge_index dtype
    for (int i = gtid; i < n; i += nthr) g_deg[i] = 0;
    if (bid == 0 && tid < 32) {
        int z = 0;
        if (ei_w[2 * tid + 1] == 0) z++;
        if (ei_w[2 * (tid + 32) + 1] == 0) z++;
#pragma unroll
        for (int o = 16; o > 0; o >>= 1)
            z += __shfl_down_sync(0xffffffffu, z, o);
        if (tid == 0) g_is64 = (z >= 60) ? 1 : 0;
    }
    grid_sync(0, nb);

    // phase 1: degree histogram
    int stride = g_is64 ? 2 : 1;
    for (int i = gtid; i < E; i += nthr) {
        int s = ei_w[(size_t)i * stride];
        int d = ei_w[(size_t)(E + i) * stride];
        atomicAdd(&g_deg[s], 1);
        atomicAdd(&g_deg[d], 1);
    }
    grid_sync(1, nb);

    // phase 2: exclusive scan of degrees (block-local + lookback)
    int i = gtid;
    int v = (i < n) ? g_deg[i] : 0;
    int s = v;
#pragma unroll
    for (int o = 1; o < 32; o <<= 1) {
        int t = __shfl_up_sync(0xffffffffu, s, o);
        if (lane >= o) s += t;
    }
    if (lane == 31) ws[wid] = s;
    __syncthreads();
    if (wid == 0 && lane < 16) {
        int t = ws[lane];
        int ss = t;
#pragma unroll
        for (int o = 1; o < 16; o <<= 1) {
            int u = __shfl_up_sync(0x0000ffffu, ss, o);
            if (lane >= o) ss += u;
        }
        ws[lane] = ss - t;
    }
    __syncthreads();
    int excl = ws[wid] + s - v;          // block-local exclusive prefix
    if (tid == BLD_BLK - 1) {            // publish block aggregate
        g_aggr[bid] = excl + v;
        __threadfence();
        g_flag[bid] = 1;
    }
    if (wid == 0) {                      // lookback over earlier blocks
        int base = 0;
        for (int j = lane; j < bid; j += 32) {
            while (g_flag[j] == 0) { }
            base += g_aggr[j];
        }
#pragma unroll
        for (int o = 16; o > 0; o >>= 1)
            base += __shfl_down_sync(0xffffffffu, base, o);
        if (lane == 0) sbase = base;
    }
    __syncthreads();
    if (i < n) {
        g_off[i]  = sbase + excl;
        g_dinv[i] = (v > 0) ? rsqrtf((float)v) : 0.0f;
    }
    grid_sync(2, nb);

    // phase 3: scatter neighbor ids (advances g_off; consumer uses off - deg)
    for (int e = gtid; e < E; e += nthr) {
        int sN = ei_w[(size_t)e * stride];
        int dN = ei_w[(size_t)(E + e) * stride];
        int ps = atomicAdd(&g_off[sN], 1);
        g_adj[ps] = dN;
        int pd = atomicAdd(&g_off[dN], 1);
        g_adj[pd] = sN;
    }
}

// ---------------------------------------------------------------------------
// Kernel 2 (fused, warp-persistent): W loaded into smem ONCE per block, then
// each warp is an independent gather->GEMM pipeline over strided 8-row groups.
// No block barriers in steady state -> gather (LSU) and GEMM (FMA) phases of
// different warps overlap on the SM.
// smem: wt[128][132] transposed W (67.6KB) + xs 8 warps x 8 rows x 128
// (32KB) = 99.3KB -> 2 blocks/SM. Inner loop = R10's proven form.
// Also resets persistent-sync state for the next graph replay.
// ---------------------------------------------------------------------------
#define WT_STRIDE 132
#define GG_THREADS 256
#define GG_BLOCKS 296
#define GG_SMEM ((128 * WT_STRIDE + 64 * 128) * 4)

__global__ __launch_bounds__(GG_THREADS)
void k_gg(const float4* __restrict__ x4, const float* __restrict__ W,
          const float* __restrict__ b, float* __restrict__ out,
          int n, int ngroups) {
    extern __shared__ float sm[];
    float* wt = sm;                        // [128][WT_STRIDE] wt[k][c]=W[c][k]
    float* xs = sm + 128 * WT_STRIDE;      // [8 warps][8 rows][128]

    int tid  = threadIdx.x;
    int lane = tid & 31;
    int wrp  = tid >> 5;

    // reset build-kernel sync state for the next launch (deterministic)
    if (blockIdx.x == 0) {
        if (tid < 4) g_sctr[tid] = 0;
        for (int i = tid; i < MAX_BLD; i += GG_THREADS) g_flag[i] = 0;
    }

    // Load W transposed into smem once (coalesced LDG; 4-way STS conflict OK).
    for (int i = tid; i < 128 * 128; i += GG_THREADS) {
        int c = i >> 7, k = i & 127;
        wt[k * WT_STRIDE + c] = W[i];
    }
    __syncthreads();   // the ONLY block barrier

    float* xsw = xs + wrp * 8 * 128;       // warp-private tile
    int c0 = lane * 4;
    float4 bv = *(const float4*)(b + c0);
    int gwarp    = blockIdx.x * 8 + wrp;
    int totwarps = GG_BLOCKS * 8;

    for (int g = gwarp; g < ngroups; g += totwarps) {
        int vbase = g * 8;

        // ---- gather 8 rows into the warp-private smem tile ----
#pragma unroll 1
        for (int j = 0; j < 8; j++) {
            int v = vbase + j;
            float4 h = make_float4(0.f, 0.f, 0.f, 0.f);
            if (v < n) {
                int deg  = g_deg[v];
                int base = g_off[v] - deg;
                float4 acc = make_float4(0.f, 0.f, 0.f, 0.f);
                int e = 0;
                int deg4 = deg & ~3;
                for (; e < deg4; e += 4) {
                    int nb0 = __ldg(&g_adj[base + e]);
                    int nb1 = __ldg(&g_adj[base + e + 1]);
                    int nb2 = __ldg(&g_adj[base + e + 2]);
                    int nb3 = __ldg(&g_adj[base + e + 3]);
                    float w0 = __ldg(&g_dinv[nb0]);
                    float w1 = __ldg(&g_dinv[nb1]);
                    float w2 = __ldg(&g_dinv[nb2]);
                    float w3 = __ldg(&g_dinv[nb3]);
                    float4 v0 = __ldg(x4 + (size_t)nb0 * 32 + lane);
                    float4 v1 = __ldg(x4 + (size_t)nb1 * 32 + lane);
                    float4 v2 = __ldg(x4 + (size_t)nb2 * 32 + lane);
                    float4 v3 = __ldg(x4 + (size_t)nb3 * 32 + lane);
                    acc.x += w0 * v0.x + w1 * v1.x + w2 * v2.x + w3 * v3.x;
                    acc.y += w0 * v0.y + w1 * v1.y + w2 * v2.y + w3 * v3.y;
                    acc.z += w0 * v0.z + w1 * v1.z + w2 * v2.z + w3 * v3.z;
                    acc.w += w0 * v0.w + w1 * v1.w + w2 * v2.w + w3 * v3.w;
                }
                for (; e < deg; e++) {
                    int nb = __ldg(&g_adj[base + e]);
                    float w = __ldg(&g_dinv[nb]);
                    float4 vv = __ldg(x4 + (size_t)nb * 32 + lane);
                    acc.x += w * vv.x; acc.y += w * vv.y;
                    acc.z += w * vv.z; acc.w += w * vv.w;
                }
                float dv = g_dinv[v];
                float4 xv = __ldg(x4 + (size_t)v * 32 + lane);
                h.x = xv.x + dv * acc.x;
                h.y = xv.y + dv * acc.y;
                h.z = xv.z + dv * acc.z;
                h.w = xv.w + dv * acc.w;
            }
            *(float4*)&xsw[j * 128 + lane * 4] = h;
        }
        __syncwarp();

        // ---- GEMM vs resident W ----
        float acc[8][4];
#pragma unroll
        for (int r = 0; r < 8; r++)
#pragma unroll
            for (int c = 0; c < 4; c++) acc[r][c] = 0.0f;

#pragma unroll 4
        for (int k = 0; k < 128; k++) {
            float4 wv = *(const float4*)(wt + k * WT_STRIDE + c0);
#pragma unroll
            for (int r = 0; r < 8; r++) {
                float a = xsw[r * 128 + k];    // warp-uniform broadcast
                acc[r][0] += a * wv.x;
                acc[r][1] += a * wv.y;
                acc[r][2] += a * wv.z;
                acc[r][3] += a * wv.w;
            }
        }

#pragma unroll
        for (int r = 0; r < 8; r++) {
            int row = vbase + r;
            if (row < n) {
                float4 o;
                o.x = fmaxf(acc[r][0] + bv.x, 0.0f);
                o.y = fmaxf(acc[r][1] + bv.y, 0.0f);
                o.z = fmaxf(acc[r][2] + bv.z, 0.0f);
                o.w = fmaxf(acc[r][3] + bv.w, 0.0f);
                *(float4*)(out + (size_t)row * DFEAT + c0) = o;
            }
        }
        __syncwarp();   // xsw reuse safety before next gather
    }
}

// ---------------------------------------------------------------------------
// kernel_launch
// inputs: 0=x [N,128] f32, 1=edge_index [2,E] int32/int64, 2=W [128,128], 3=b [128]
// ---------------------------------------------------------------------------
extern "C" void kernel_launch(void* const* d_in, const int* in_sizes, int n_in,
                              void* d_out, int out_size) {
    const float* x    = (const float*)d_in[0];
    const int*   ei_w = (const int*)d_in[1];
    const float* W    = (const float*)d_in[2];
    const float* b    = (const float*)d_in[3];
    float*       out  = (float*)d_out;

    int n = in_sizes[0] / DFEAT;
    int E = in_sizes[1] / 2;
    int ngroups = (n + 7) / 8;

    int nb = BLD_NB;
    int need = (n + BLD_BLK - 1) / BLD_BLK;
    if (need > nb) nb = need;

    k_build<<<nb, BLD_BLK>>>(ei_w, n, E, nb);

    cudaFuncSetAttribute(k_gg, cudaFuncAttributeMaxDynamicSharedMemorySize,
                         GG_SMEM);
    k_gg<<<GG_BLOCKS, GG_THREADS, GG_SMEM>>>(
        (const float4*)x, W, b, out, n, ngroups);
}

// round 16
// speedup vs baseline: 1.1323x; 1.1323x over previous
#include <cuda_runtime.h>
#include <cuda_bf16.h>
#include <cstdint>

#define DFEAT 128
#define MAX_NODES 100000
#define MAX_EDGES 650000
#define BLD_BLK 512
#define BLD_NB  444          // 3 blocks/SM on 148 SMs; all co-resident
#define MAX_BLD 512

// scratch (static __device__ arrays — no allocations allowed)
__device__ int          g_deg[MAX_NODES];
__device__ int          g_off[MAX_NODES];
__device__ float        g_dinv[MAX_NODES];
__device__ int          g_adj[2 * MAX_EDGES];
// persistent-kernel sync state; statically zero, re-zeroed by k_gg each launch
__device__ volatile int g_sctr[4];
__device__ volatile int g_flag[MAX_BLD];
__device__ volatile int g_aggr[MAX_BLD];
__device__ int          g_is64;

// ---------------------------------------------------------------------------
// Grid sync via atomic counter + spin. SAFE only because all BLD_NB blocks
// are co-resident (444 = 3/SM, 512 thr).
// ---------------------------------------------------------------------------
__device__ __forceinline__ void grid_sync(int k, int nb) {
    __syncthreads();
    if (threadIdx.x == 0) {
        __threadfence();
        atomicAdd((int*)&g_sctr[k], 1);
        while (g_sctr[k] < nb) { }
        __threadfence();
    }
    __syncthreads();
}

// ---------------------------------------------------------------------------
// Kernel 1 (fused persistent): zero+detect -> histogram -> scan(+dinv) -> scatter
// ---------------------------------------------------------------------------
__global__ __launch_bounds__(BLD_BLK)
void k_build(const int* __restrict__ ei_w, int n, int E, int nb) {
    __shared__ int ws[16];
    __shared__ int sbase;
    int tid  = threadIdx.x;
    int bid  = blockIdx.x;
    int lane = tid & 31, wid = tid >> 5;
    int gtid = bid * BLD_BLK + tid;
    int nthr = nb * BLD_BLK;

    // phase 0: zero degree counters; block 0 detects edge_index dtype
    for (int i = gtid; i < n; i += nthr) g_deg[i] = 0;
    if (bid == 0 && tid < 32) {
        int z = 0;
        if (ei_w[2 * tid + 1] == 0) z++;
        if (ei_w[2 * (tid + 32) + 1] == 0) z++;
#pragma unroll
        for (int o = 16; o > 0; o >>= 1)
            z += __shfl_down_sync(0xffffffffu, z, o);
        if (tid == 0) g_is64 = (z >= 60) ? 1 : 0;
    }
    grid_sync(0, nb);

    // phase 1: degree histogram
    int stride = g_is64 ? 2 : 1;
    for (int i = gtid; i < E; i += nthr) {
        int s = ei_w[(size_t)i * stride];
        int d = ei_w[(size_t)(E + i) * stride];
        atomicAdd(&g_deg[s], 1);
        atomicAdd(&g_deg[d], 1);
    }
    grid_sync(1, nb);

    // phase 2: exclusive scan of degrees (block-local + lookback)
    int i = gtid;
    int v = (i < n) ? g_deg[i] : 0;
    int s = v;
#pragma unroll
    for (int o = 1; o < 32; o <<= 1) {
        int t = __shfl_up_sync(0xffffffffu, s, o);
        if (lane >= o) s += t;
    }
    if (lane == 31) ws[wid] = s;
    __syncthreads();
    if (wid == 0 && lane < 16) {
        int t = ws[lane];
        int ss = t;
#pragma unroll
        for (int o = 1; o < 16; o <<= 1) {
            int u = __shfl_up_sync(0x0000ffffu, ss, o);
            if (lane >= o) ss += u;
        }
        ws[lane] = ss - t;
    }
    __syncthreads();
    int excl = ws[wid] + s - v;          // block-local exclusive prefix
    if (tid == BLD_BLK - 1) {            // publish block aggregate
        g_aggr[bid] = excl + v;
        __threadfence();
        g_flag[bid] = 1;
    }
    if (wid == 0) {                      // lookback over earlier blocks
        int base = 0;
        for (int j = lane; j < bid; j += 32) {
            while (g_flag[j] == 0) { }
            base += g_aggr[j];
        }
#pragma unroll
        for (int o = 16; o > 0; o >>= 1)
            base += __shfl_down_sync(0xffffffffu, base, o);
        if (lane == 0) sbase = base;
    }
    __syncthreads();
    if (i < n) {
        g_off[i]  = sbase + excl;
        g_dinv[i] = (v > 0) ? rsqrtf((float)v) : 0.0f;
    }
    grid_sync(2, nb);

    // phase 3: scatter neighbor ids (advances g_off; consumer uses off - deg)
    for (int e = gtid; e < E; e += nthr) {
        int sN = ei_w[(size_t)e * stride];
        int dN = ei_w[(size_t)(E + e) * stride];
        int ps = atomicAdd(&g_off[sN], 1);
        g_adj[ps] = dN;
        int pd = atomicAdd(&g_off[dN], 1);
        g_adj[pd] = sN;
    }
}

// ---------------------------------------------------------------------------
// Kernel 2 (fused): gather aggregation into smem tile, then
// out = relu(h @ W^T + b).  R10 structure exactly (256 thr, 64 rows,
// KCHUNK=16 W staging, scalar-broadcast inner loop, natural regs) with ONE
// change: the gather edge loop software-pipelines the adjacency-id loads so
// next-iteration id latency hides under current x-row loads.
// smem = 64*128*4 (xs) + 16*132*4 (wt) = 41216 B.
// Also resets persistent-sync state for the next graph replay.
// ---------------------------------------------------------------------------
#define WT_STRIDE 132
#define KCHUNK 16
#define GROWS 64
#define GG_SMEM ((KCHUNK * WT_STRIDE + GROWS * 128) * 4)

__global__ __launch_bounds__(256)
void k_gg(const float4* __restrict__ x4, const float* __restrict__ W,
          const float* __restrict__ b, float* __restrict__ out, int n) {
    extern __shared__ float sm[];
    float* wt = sm;                       // [KCHUNK][WT_STRIDE]
    float* xs = sm + KCHUNK * WT_STRIDE;  // [GROWS][128]

    int tid  = threadIdx.x;
    int lane = tid & 31;
    int wrp  = tid >> 5;
    int row0 = blockIdx.x * GROWS;

    // reset build-kernel sync state for the next launch (deterministic)
    if (blockIdx.x == 0) {
        if (tid < 4) g_sctr[tid] = 0;
        for (int i = tid; i < MAX_BLD; i += 256) g_flag[i] = 0;
    }

    // ---- gather phase: each warp produces 8 rows of the h tile ----
#pragma unroll 1
    for (int j = 0; j < 8; j++) {
        int r = wrp * 8 + j;
        int v = row0 + r;
        float4 h = make_float4(0.f, 0.f, 0.f, 0.f);
        if (v < n) {
            int deg  = g_deg[v];
            int base = g_off[v] - deg;
            float4 acc = make_float4(0.f, 0.f, 0.f, 0.f);
            int deg4 = deg & ~3;
            // software-pipelined 4-edge loop: prefetch next ids before
            // consuming current ones, so id latency hides under x loads.
            int nb0 = 0, nb1 = 0, nb2 = 0, nb3 = 0;
            if (deg4 > 0) {
                nb0 = __ldg(&g_adj[base]);
                nb1 = __ldg(&g_adj[base + 1]);
                nb2 = __ldg(&g_adj[base + 2]);
                nb3 = __ldg(&g_adj[base + 3]);
            }
            for (int e = 0; e < deg4; e += 4) {
                int m0, m1, m2, m3;
                bool more = (e + 8 <= deg4);
                if (more) {
                    m0 = __ldg(&g_adj[base + e + 4]);
                    m1 = __ldg(&g_adj[base + e + 5]);
                    m2 = __ldg(&g_adj[base + e + 6]);
                    m3 = __ldg(&g_adj[base + e + 7]);
                }
                float w0 = __ldg(&g_dinv[nb0]);
                float w1 = __ldg(&g_dinv[nb1]);
                float w2 = __ldg(&g_dinv[nb2]);
                float w3 = __ldg(&g_dinv[nb3]);
                float4 v0 = __ldg(x4 + (size_t)nb0 * 32 + lane);
                float4 v1 = __ldg(x4 + (size_t)nb1 * 32 + lane);
                float4 v2 = __ldg(x4 + (size_t)nb2 * 32 + lane);
                float4 v3 = __ldg(x4 + (size_t)nb3 * 32 + lane);
                acc.x += w0 * v0.x + w1 * v1.x + w2 * v2.x + w3 * v3.x;
                acc.y += w0 * v0.y + w1 * v1.y + w2 * v2.y + w3 * v3.y;
                acc.z += w0 * v0.z + w1 * v1.z + w2 * v2.z + w3 * v3.z;
                acc.w += w0 * v0.w + w1 * v1.w + w2 * v2.w + w3 * v3.w;
                if (more) { nb0 = m0; nb1 = m1; nb2 = m2; nb3 = m3; }
            }
            for (int e = deg4; e < deg; e++) {
                int nb = __ldg(&g_adj[base + e]);
                float w = __ldg(&g_dinv[nb]);
                float4 vv = __ldg(x4 + (size_t)nb * 32 + lane);
                acc.x += w * vv.x; acc.y += w * vv.y;
                acc.z += w * vv.z; acc.w += w * vv.w;
            }
            float dv = g_dinv[v];
            float4 xv = __ldg(x4 + (size_t)v * 32 + lane);
            h.x = xv.x + dv * acc.x;
            h.y = xv.y + dv * acc.y;
            h.z = xv.z + dv * acc.z;
            h.w = xv.w + dv * acc.w;
        }
        *(float4*)&xs[r * 128 + lane * 4] = h;
    }

    // ---- GEMM phase (R10 inner loop, untouched) ----
    int r0 = wrp * 8;
    int c0 = lane * 4;

    float acc[8][4];
#pragma unroll
    for (int r = 0; r < 8; r++)
#pragma unroll
        for (int c = 0; c < 4; c++) acc[r][c] = 0.0f;

    for (int k0 = 0; k0 < 128; k0 += KCHUNK) {
        __syncthreads();
        for (int i = tid; i < 128 * KCHUNK; i += 256) {
            int j  = i >> 4;
            int kk = i & (KCHUNK - 1);
            wt[kk * WT_STRIDE + j] = W[j * 128 + k0 + kk];
        }
        __syncthreads();

#pragma unroll
        for (int kk = 0; kk < KCHUNK; kk++) {
            int k = k0 + kk;
            float4 wv = *(const float4*)(wt + kk * WT_STRIDE + c0);
#pragma unroll
            for (int r = 0; r < 8; r++) {
                float a = xs[(r0 + r) * 128 + k];   // warp-uniform broadcast
                acc[r][0] += a * wv.x;
                acc[r][1] += a * wv.y;
                acc[r][2] += a * wv.z;
                acc[r][3] += a * wv.w;
            }
        }
    }

    float4 bv = *(const float4*)(b + c0);
#pragma unroll
    for (int r = 0; r < 8; r++) {
        int row = row0 + r0 + r;
        if (row < n) {
            float4 o;
            o.x = fmaxf(acc[r][0] + bv.x, 0.0f);
            o.y = fmaxf(acc[r][1] + bv.y, 0.0f);
            o.z = fmaxf(acc[r][2] + bv.z, 0.0f);
            o.w = fmaxf(acc[r][3] + bv.w, 0.0f);
            *(float4*)(out + (size_t)row * DFEAT + c0) = o;
        }
    }
}

// ---------------------------------------------------------------------------
// kernel_launch
// inputs: 0=x [N,128] f32, 1=edge_index [2,E] int32/int64, 2=W [128,128], 3=b [128]
// ---------------------------------------------------------------------------
extern "C" void kernel_launch(void* const* d_in, const int* in_sizes, int n_in,
                              void* d_out, int out_size) {
    const float* x    = (const float*)d_in[0];
    const int*   ei_w = (const int*)d_in[1];
    const float* W    = (const float*)d_in[2];
    const float* b    = (const float*)d_in[3];
    float*       out  = (float*)d_out;

    int n = in_sizes[0] / DFEAT;
    int E = in_sizes[1] / 2;

    int nb = BLD_NB;
    int need = (n + BLD_BLK - 1) / BLD_BLK;
    if (need > nb) nb = need;

    k_build<<<nb, BLD_BLK>>>(ei_w, n, E, nb);
    k_gg<<<(n + GROWS - 1) / GROWS, 256, GG_SMEM>>>(
        (const float4*)x, W, b, out, n);
}